// round 6
// baseline (speedup 1.0000x reference)
#include <cuda_runtime.h>
#include <cstdint>

#define BB    2048
#define TT    64
#define CC    1024
#define HH    16
#define DKK   8
#define M1M   512
#define M2M   128
#define SCALE_ 0.35355339059327373f
#define EPS_   1e-5f
#define NEGINF_ (-3.402823466e38f)

// ---------------- device scratch (no allocations allowed) ----------------
__device__ float g_wq[HH * CC];          // 64 KB  : folded query projection (scaled)
__device__ float g_pooled[BB * CC];      // 8 MB   : attention-pooled features
__device__ int   g_mask_mode;            // 0=u8, 1=i32, 2=f32
__device__ volatile int g_done;          // gate counter (monotone across replays)

// ---------------- f32x2 packed-math helpers ----------------
__device__ __forceinline__ void upk2(unsigned long long v, float& lo, float& hi) {
    asm("mov.b64 {%0,%1}, %2;" : "=f"(lo), "=f"(hi) : "l"(v));
}
__device__ __forceinline__ unsigned long long fma2(unsigned long long a,
                                                   unsigned long long b,
                                                   unsigned long long c) {
    unsigned long long d;
    asm("fma.rn.f32x2 %0, %1, %2, %3;" : "=l"(d) : "l"(a), "l"(b), "l"(c));
    return d;
}

// ---------------- K1: gated wq precompute + scores + flash softmax + pooling ----
// smem floats: wq[16384] | xs[2][16384] | att[1024] | p[256] | mrun[16] srun[16]
//              fsc[16] | msk[64]
#define WQ_OFF   0
#define XS_OFF   16384
#define ATT_OFF  49152
#define P_OFF    50176
#define MR_OFF   50432
#define SR_OFF   50448
#define FS_OFF   50464
#define MSK_OFF  50480
#define SMEM1_F  50544

__device__ __forceinline__ void tile_async(float* dst, const float* src) {
    int tid = threadIdx.x;
    #pragma unroll
    for (int i = 0; i < 16; i++) {
        int e = (tid + i * 256) * 4;
        uint32_t sa = (uint32_t)__cvta_generic_to_shared(dst + e);
        asm volatile("cp.async.cg.shared.global [%0], [%1], 16;\n"
                     :: "r"(sa), "l"(src + e));
    }
}

__global__ void __launch_bounds__(256, 1)
k_attn(const float* __restrict__ x, const void* __restrict__ kpm,
       const float* __restrict__ Wk, const float* __restrict__ query,
       float* __restrict__ attn_out) {
    extern __shared__ float smem[];
    float* wq_s  = smem + WQ_OFF;
    float* xs    = smem + XS_OFF;
    float* att_s = smem + ATT_OFF;
    float* p_s   = smem + P_OFF;
    float* mrun  = smem + MR_OFF;
    float* srun  = smem + SR_OFF;
    float* fsc   = smem + FS_OFF;
    int*   msk_s = (int*)(smem + MSK_OFF);

    const int b    = blockIdx.x;
    const int tid  = threadIdx.x;
    const int wid  = tid >> 5;
    const int lane = tid & 31;
    const float* xb = x + (size_t)b * (TT * CC);

    // ================= producer phase: blocks 0..15 build g_wq (+ mask mode) =====
    if (b < 16) {
        float* wk_s = xs;                 // reuse x staging area (32 KB)
        float* q_s  = att_s;              // 128 floats
        const int c_base = b * 64;
        const float4* src = (const float4*)(Wk + c_base * (HH * DKK));
        #pragma unroll
        for (int i = 0; i < 8; i++)
            ((float4*)wk_s)[tid + i * 256] = src[tid + i * 256];
        if (tid < 128) q_s[tid] = query[tid] * SCALE_;
        __syncthreads();
        const int h  = tid >> 4;
        const int cl = (tid & 15) * 4;
        #pragma unroll
        for (int j = 0; j < 4; j++) {
            float s = 0.f;
            #pragma unroll
            for (int d = 0; d < DKK; d++)
                s += q_s[h * DKK + d] * wk_s[(cl + j) * 128 + h * DKK + d];
            g_wq[h * CC + c_base + cl + j] = s;
        }
        if (b == 0) {
            // mask dtype fingerprint over first 32768 bytes
            __shared__ int nonbin, oddpos;
            if (tid == 0) { nonbin = 0; oddpos = 0; }
            __syncthreads();
            const unsigned char* p = (const unsigned char*)kpm;
            int lnb = 0, lod = 0;
            int base = tid * 128;
            for (int i = 0; i < 128; i++) {
                unsigned char v = p[base + i];
                if (v > 1) lnb = 1;
                else if (v == 1 && ((base + i) & 3)) lod = 1;
            }
            if (lnb) atomicOr(&nonbin, 1);
            if (lod) atomicOr(&oddpos, 1);
            __syncthreads();
            if (tid == 0) g_mask_mode = nonbin ? 2 : (oddpos ? 0 : 1);
        }
        __threadfence();
        __syncthreads();
        if (tid == 0) atomicAdd((int*)&g_done, 1);
    } else {
        // workers: overlap tile-0 prefetch with the gate spin
        tile_async(xs, xb);
        asm volatile("cp.async.commit_group;\n");
    }

    // ================= gate =================
    if (tid == 0) { while (g_done < 16) { } }
    __syncthreads();
    __threadfence();

    if (b < 16) {                      // producers start their prefetch now
        tile_async(xs, xb);
        asm volatile("cp.async.commit_group;\n");
    }

    // stage wq (coalesced float4)
    #pragma unroll 4
    for (int i = tid; i < 4096; i += 256)
        ((float4*)wq_s)[i] = ((const float4*)g_wq)[i];

    const int mode = g_mask_mode;
    if (tid < TT) {
        int mv;
        if (mode == 0)      mv = ((const unsigned char*)kpm)[b * TT + tid] != 0;
        else if (mode == 1) mv = ((const int*)kpm)[b * TT + tid] != 0;
        else                mv = ((const float*)kpm)[b * TT + tid] != 0.f;
        msk_s[tid] = mv;
    }
    if (tid < HH) { mrun[tid] = NEGINF_; srun[tid] = 0.f; }

    const int rg = (wid & 3) * 4;       // 4 rows within tile
    const int h0 = (wid >> 2) * 8;      // 8 heads

    float4 pacc = make_float4(0.f, 0.f, 0.f, 0.f);
    const int hc = tid >> 4;            // head owning channels [tid*4, tid*4+4)

    for (int tile = 0; tile < 4; tile++) {
        if (tile < 3) {
            tile_async(xs + ((tile + 1) & 1) * 16384, xb + (tile + 1) * 16384);
            asm volatile("cp.async.commit_group;\n");
            asm volatile("cp.async.wait_group 1;\n");
        } else {
            asm volatile("cp.async.wait_group 0;\n");
        }
        __syncthreads();

        float* xt = xs + (tile & 1) * 16384;
        // ulonglong2 views: one LDS.128 == two packed f32x2 operands, zero movs
        const ulonglong2* xr0 = (const ulonglong2*)(xt + (rg + 0) * CC);
        const ulonglong2* xr1 = (const ulonglong2*)(xt + (rg + 1) * CC);
        const ulonglong2* xr2 = (const ulonglong2*)(xt + (rg + 2) * CC);
        const ulonglong2* xr3 = (const ulonglong2*)(xt + (rg + 3) * CC);
        const ulonglong2* wqp = (const ulonglong2*)(wq_s + h0 * CC);

        unsigned long long acc[4][8];
        #pragma unroll
        for (int r = 0; r < 4; r++)
            #pragma unroll
            for (int h = 0; h < 8; h++) acc[r][h] = 0ull;

        #pragma unroll
        for (int it = 0; it < 8; it++) {
            const int ci = lane + it * 32;           // ulonglong2 index (16B each)
            ulonglong2 X0 = xr0[ci];
            ulonglong2 X1 = xr1[ci];
            ulonglong2 X2 = xr2[ci];
            ulonglong2 X3 = xr3[ci];
            #pragma unroll
            for (int h = 0; h < 8; h++) {
                ulonglong2 W = wqp[h * (CC / 4) + ci];
                acc[0][h] = fma2(X0.x, W.x, acc[0][h]); acc[0][h] = fma2(X0.y, W.y, acc[0][h]);
                acc[1][h] = fma2(X1.x, W.x, acc[1][h]); acc[1][h] = fma2(X1.y, W.y, acc[1][h]);
                acc[2][h] = fma2(X2.x, W.x, acc[2][h]); acc[2][h] = fma2(X2.y, W.y, acc[2][h]);
                acc[3][h] = fma2(X3.x, W.x, acc[3][h]); acc[3][h] = fma2(X3.y, W.y, acc[3][h]);
            }
        }

        // staggered per-row reduction
        #pragma unroll
        for (int r = 0; r < 4; r++) {
            float sv[8];
            #pragma unroll
            for (int h = 0; h < 8; h++) {
                float lo, hi; upk2(acc[r][h], lo, hi);
                sv[h] = lo + hi;
            }
            #pragma unroll
            for (int off = 16; off; off >>= 1)
                #pragma unroll
                for (int h = 0; h < 8; h++)
                    sv[h] += __shfl_xor_sync(0xffffffffu, sv[h], off);
            float v = sv[0];
            #pragma unroll
            for (int h = 1; h < 8; h++) v = (lane == h) ? sv[h] : v;
            if (lane < 8)
                att_s[(h0 + lane) * TT + tile * 16 + rg + r] = v;
        }
        __syncthreads();

        // ---- flash update: warp w handles heads 2w, 2w+1 (16 lanes each) ----
        {
            const int h  = wid * 2 + (lane >> 4);
            const int tt = lane & 15;
            const int tg = tile * 16 + tt;
            float s_raw  = att_s[h * TT + tg];
            int   msk    = msk_s[tg];
            float sm     = msk ? NEGINF_ : s_raw;
            float tmax   = sm;
            #pragma unroll
            for (int off = 8; off; off >>= 1)
                tmax = fmaxf(tmax, __shfl_xor_sync(0xffffffffu, tmax, off));
            float m_old = mrun[h];
            float m_new = fmaxf(m_old, tmax);
            float p     = msk ? 0.f : __expf(s_raw - m_new);
            float psum  = p;
            #pragma unroll
            for (int off = 8; off; off >>= 1)
                psum += __shfl_xor_sync(0xffffffffu, psum, off);
            float f = __expf(m_old - m_new);
            p_s[h * 16 + tt] = p;
            if ((lane & 15) == 0) {
                mrun[h] = m_new;
                srun[h] = srun[h] * f + psum;
                fsc[h]  = f;
            }
        }
        __syncthreads();

        // ---- pooled accumulation from resident smem tile ----
        {
            float f = fsc[hc];
            pacc.x *= f; pacc.y *= f; pacc.z *= f; pacc.w *= f;
            const float* xp = xt + tid * 4;
            const float* pp = p_s + hc * 16;
            #pragma unroll
            for (int t = 0; t < 16; t++) {
                float p = pp[t];
                float4 v = *(const float4*)(xp + t * CC);
                pacc.x += p * v.x; pacc.y += p * v.y;
                pacc.z += p * v.z; pacc.w += p * v.w;
            }
        }
        __syncthreads();
    }

    // ---- finalize ----
    {
        const int h  = tid >> 4;
        const int t4 = (tid & 15) * 4;
        float m   = mrun[h];
        float inv = 1.f / srun[h];
        float4 o;
        float* op = &o.x;
        #pragma unroll
        for (int j = 0; j < 4; j++) {
            int t = t4 + j;
            op[j] = msk_s[t] ? 0.f : __expf(att_s[h * TT + t] - m) * inv;
        }
        *(float4*)(attn_out + (size_t)b * (HH * TT) + h * TT + t4) = o;

        float invp = 1.f / srun[hc];
        pacc.x *= invp; pacc.y *= invp; pacc.z *= invp; pacc.w *= invp;
        *(float4*)(g_pooled + (size_t)b * CC + tid * 4) = pacc;
    }
}

// ---------------- K2: MLP (GEMM1 + LN + ReLU + GEMM2 + LN + ReLU) ----------------
#define PT_OFF   0
#define PT_STR   18
#define YS_OFF   18432
#define Y2_OFF   26624
#define ST_OFF   28672
#define SMEM2_F  28736

__device__ __forceinline__ unsigned long long pk2(float lo, float hi) {
    unsigned long long r;
    asm("mov.b64 %0, {%1,%2};" : "=l"(r) : "f"(lo), "f"(hi));
    return r;
}

__global__ void __launch_bounds__(256, 1)
k_mlp(const float* __restrict__ W1, const float* __restrict__ g1,
      const float* __restrict__ b1, const float* __restrict__ W2,
      const float* __restrict__ g2, const float* __restrict__ b2,
      float* __restrict__ out) {
    extern __shared__ float smem[];
    float* pt  = smem + PT_OFF;
    float* ys  = smem + YS_OFF;
    float* y2s = smem + Y2_OFF;
    float* mu1 = smem + ST_OFF;
    float* rs1 = mu1 + 16;
    float* mu2 = rs1 + 16;
    float* rs2 = mu2 + 16;

    const int b0   = blockIdx.x * 16;
    const int tid  = threadIdx.x;
    const int wid  = tid >> 5;
    const int lane = tid & 31;

    for (int i = tid; i < 4096; i += 256) {
        int r  = i >> 8;
        int k4 = (i & 255) * 4;
        float4 v = *(const float4*)(g_pooled + (size_t)(b0 + r) * CC + k4);
        pt[(k4 + 0) * PT_STR + r] = v.x;
        pt[(k4 + 1) * PT_STR + r] = v.y;
        pt[(k4 + 2) * PT_STR + r] = v.z;
        pt[(k4 + 3) * PT_STR + r] = v.w;
    }
    __syncthreads();

    unsigned long long acc[16];
    #pragma unroll
    for (int r = 0; r < 16; r++) acc[r] = 0ull;
    const float2* w1p = (const float2*)W1 + tid;
    #pragma unroll 4
    for (int k = 0; k < CC; k++) {
        float2 w = w1p[k * (M1M / 2)];
        unsigned long long wp = pk2(w.x, w.y);
        const float* ptk = pt + k * PT_STR;
        #pragma unroll
        for (int rp = 0; rp < 8; rp++) {
            float2 xv = *(const float2*)(ptk + rp * 2);
            acc[2 * rp]     = fma2(pk2(xv.x, xv.x), wp, acc[2 * rp]);
            acc[2 * rp + 1] = fma2(pk2(xv.y, xv.y), wp, acc[2 * rp + 1]);
        }
    }
    #pragma unroll
    for (int r = 0; r < 16; r++) {
        float lo, hi; upk2(acc[r], lo, hi);
        *(float2*)(ys + r * M1M + 2 * tid) = make_float2(lo, hi);
    }
    __syncthreads();

    for (int r = wid; r < 16; r += 8) {
        float s = 0.f, ss = 0.f;
        #pragma unroll
        for (int j = 0; j < 16; j++) {
            float v = ys[r * M1M + lane + j * 32];
            s += v; ss += v * v;
        }
        #pragma unroll
        for (int off = 16; off; off >>= 1) {
            s  += __shfl_xor_sync(0xffffffffu, s, off);
            ss += __shfl_xor_sync(0xffffffffu, ss, off);
        }
        if (lane == 0) {
            float mu = s * (1.f / M1M);
            float var = ss * (1.f / M1M) - mu * mu;
            mu1[r] = mu;
            rs1[r] = rsqrtf(var + EPS_);
        }
    }
    __syncthreads();

    {
        float2 gv = ((const float2*)g1)[tid];
        float2 bv = ((const float2*)b1)[tid];
        #pragma unroll
        for (int r = 0; r < 16; r++) {
            float m = mu1[r], rs = rs1[r];
            float2 v = *(float2*)(ys + r * M1M + 2 * tid);
            v.x = fmaxf(0.f, (v.x - m) * rs * gv.x + bv.x);
            v.y = fmaxf(0.f, (v.y - m) * rs * gv.y + bv.y);
            *(float2*)(ys + r * M1M + 2 * tid) = v;
        }
    }
    __syncthreads();

    const int m  = tid & 127;
    const int rb = (tid >> 7) * 8;
    {
        float a2[8];
        #pragma unroll
        for (int j = 0; j < 8; j++) a2[j] = 0.f;
        #pragma unroll 2
        for (int k = 0; k < M1M; k++) {
            float w = W2[k * M2M + m];
            const float* yk = ys + rb * M1M + k;
            #pragma unroll
            for (int j = 0; j < 8; j++) a2[j] += yk[j * M1M] * w;
        }
        #pragma unroll
        for (int j = 0; j < 8; j++) y2s[(rb + j) * M2M + m] = a2[j];
    }
    __syncthreads();

    for (int r = wid; r < 16; r += 8) {
        float s = 0.f, ss = 0.f;
        #pragma unroll
        for (int j = 0; j < 4; j++) {
            float v = y2s[r * M2M + lane + j * 32];
            s += v; ss += v * v;
        }
        #pragma unroll
        for (int off = 16; off; off >>= 1) {
            s  += __shfl_xor_sync(0xffffffffu, s, off);
            ss += __shfl_xor_sync(0xffffffffu, ss, off);
        }
        if (lane == 0) {
            float mu = s * (1.f / M2M);
            float var = ss * (1.f / M2M) - mu * mu;
            mu2[r] = mu;
            rs2[r] = rsqrtf(var + EPS_);
        }
    }
    __syncthreads();

    {
        float gv = g2[m], bv = b2[m];
        #pragma unroll
        for (int j = 0; j < 8; j++) {
            int r = rb + j;
            float v = (y2s[r * M2M + m] - mu2[r]) * rs2[r] * gv + bv;
            out[(size_t)(b0 + r) * M2M + m] = fmaxf(0.f, v);
        }
    }
}

// ---------------- launcher ----------------
extern "C" void kernel_launch(void* const* d_in, const int* in_sizes, int n_in,
                              void* d_out, int out_size) {
    const float* x     = (const float*)d_in[0];
    const void*  kpm   = d_in[2];
    const float* Wk    = (const float*)d_in[3];
    const float* query = (const float*)d_in[5];
    const float* W1    = (const float*)d_in[6];
    const float* g1    = (const float*)d_in[7];
    const float* b1    = (const float*)d_in[8];
    const float* W2    = (const float*)d_in[9];
    const float* g2    = (const float*)d_in[10];
    const float* b2    = (const float*)d_in[11];

    float* out_mlp  = (float*)d_out;                       // [B, 128]
    float* out_attn = (float*)d_out + (size_t)BB * M2M;    // [B, H, T]

    cudaFuncSetAttribute(k_attn, cudaFuncAttributeMaxDynamicSharedMemorySize,
                         SMEM1_F * 4);
    cudaFuncSetAttribute(k_mlp, cudaFuncAttributeMaxDynamicSharedMemorySize,
                         SMEM2_F * 4);

    k_attn<<<BB, 256, SMEM1_F * 4>>>(x, kpm, Wk, query, out_attn);
    k_mlp<<<BB / 16, 256, SMEM2_F * 4>>>(W1, g1, b1, W2, g2, b2, out_mlp);
}

// round 7
// speedup vs baseline: 1.4047x; 1.4047x over previous
#include <cuda_runtime.h>
#include <cstdint>

#define BB    2048
#define TT    64
#define CC    1024
#define HH    16
#define DKK   8
#define M1M   512
#define M2M   128
#define GRID_ 148
#define SCALE_ 0.35355339059327373f
#define EPS_   1e-5f
#define NEGINF_ (-3.402823466e38f)

// ---------------- device scratch (no allocations allowed) ----------------
__device__ float g_wq[HH * CC];          // folded query projection (scaled)
__device__ float g_pooled[BB * CC];      // attention-pooled features
__device__ int   g_mask_mode;            // 0=u8, 1=i32, 2=f32
__device__ unsigned int g_tk1, g_tk2;    // ticket counters (monotone)
__device__ volatile unsigned int g_rl1, g_rl2;  // release rounds (monotone)

// ---------------- f32x2 packed-math helpers ----------------
__device__ __forceinline__ void upk2(unsigned long long v, float& lo, float& hi) {
    asm("mov.b64 {%0,%1}, %2;" : "=f"(lo), "=f"(hi) : "l"(v));
}
__device__ __forceinline__ unsigned long long fma2(unsigned long long a,
                                                   unsigned long long b,
                                                   unsigned long long c) {
    unsigned long long d;
    asm("fma.rn.f32x2 %0, %1, %2, %3;" : "=l"(d) : "l"(a), "l"(b), "l"(c));
    return d;
}

// ---------------- replay-safe device-wide barrier (all 148 CTAs resident) ----
__device__ __forceinline__ void gbar(unsigned int* tk, volatile unsigned int* rl) {
    __syncthreads();
    if (threadIdx.x == 0) {
        __threadfence();
        unsigned int t = atomicAdd(tk, 1u) + 1u;
        unsigned int round = (t + GRID_ - 1u) / GRID_;
        if (t == round * GRID_) {
            __threadfence();
            *rl = round;
        } else {
            while (*rl < round) { }
        }
        __threadfence();
    }
    __syncthreads();
}

// ---------------- smem layout ----------------
// phase 1 (floats): wq[16384] | xs[2][16384] | att[1024] | p[256] | mrun[16]
//                   srun[16] | fsc[16] | msk[64]
#define WQ_OFF   0
#define XS_OFF   16384
#define ATT_OFF  49152
#define P_OFF    50176
#define MR_OFF   50432
#define SR_OFF   50448
#define FS_OFF   50464
#define MSK_OFF  50480
#define SMEM_F   50544
// phase 2 (floats): A[16*1024]@0 | Wb[2][8192]@16384 | Sp[2][2048]@32768 |
//                   ys[16*512]@36864 | y2s[16*128]@45056 | stats@47104
#define P2_A     0
#define P2_WB    16384
#define P2_SP    32768
#define P2_YS    36864
#define P2_Y2    45056
#define P2_ST    47104

__device__ __forceinline__ void tile_async(float* dst, const float* src) {
    int tid = threadIdx.x;
    #pragma unroll
    for (int i = 0; i < 16; i++) {
        int e = (tid + i * 256) * 4;
        uint32_t sa = (uint32_t)__cvta_generic_to_shared(dst + e);
        asm volatile("cp.async.cg.shared.global [%0], [%1], 16;\n"
                     :: "r"(sa), "l"(src + e));
    }
}
// 8192-float (32KB) weight tile
__device__ __forceinline__ void wtile_async(float* dst, const float* src) {
    int tid = threadIdx.x;
    #pragma unroll
    for (int i = 0; i < 8; i++) {
        int e = (tid + i * 256) * 4;
        uint32_t sa = (uint32_t)__cvta_generic_to_shared(dst + e);
        asm volatile("cp.async.cg.shared.global [%0], [%1], 16;\n"
                     :: "r"(sa), "l"(src + e));
    }
}
#define CP_COMMIT() asm volatile("cp.async.commit_group;\n")
#define CP_WAIT1()  asm volatile("cp.async.wait_group 1;\n")
#define CP_WAIT0()  asm volatile("cp.async.wait_group 0;\n")

__global__ void __launch_bounds__(256, 1)
k_fused(const float* __restrict__ x, const void* __restrict__ kpm,
        const float* __restrict__ Wk, const float* __restrict__ query,
        const float* __restrict__ W1, const float* __restrict__ g1,
        const float* __restrict__ b1, const float* __restrict__ W2,
        const float* __restrict__ g2, const float* __restrict__ b2,
        float* __restrict__ attn_out, float* __restrict__ out_mlp) {
    extern __shared__ float smem[];
    const int cta  = blockIdx.x;
    const int tid  = threadIdx.x;
    const int wid  = tid >> 5;
    const int lane = tid & 31;

    // ============ phase 0: CTAs 0..15 build g_wq; CTA0 mask fingerprint ======
    if (cta < 16) {
        float* wk_s = smem + XS_OFF;       // scratch
        float* q_s  = smem + ATT_OFF;
        const int c_base = cta * 64;
        const float4* src = (const float4*)(Wk + c_base * (HH * DKK));
        #pragma unroll
        for (int i = 0; i < 8; i++)
            ((float4*)wk_s)[tid + i * 256] = src[tid + i * 256];
        if (tid < 128) q_s[tid] = query[tid] * SCALE_;
        __syncthreads();
        const int h  = tid >> 4;
        const int cl = (tid & 15) * 4;
        #pragma unroll
        for (int j = 0; j < 4; j++) {
            float s = 0.f;
            #pragma unroll
            for (int d = 0; d < DKK; d++)
                s += q_s[h * DKK + d] * wk_s[(cl + j) * 128 + h * DKK + d];
            g_wq[h * CC + c_base + cl + j] = s;
        }
        if (cta == 0) {
            __shared__ int nonbin, oddpos;
            if (tid == 0) { nonbin = 0; oddpos = 0; }
            __syncthreads();
            const unsigned char* p = (const unsigned char*)kpm;
            int lnb = 0, lod = 0;
            int base = tid * 128;
            for (int i = 0; i < 128; i++) {
                unsigned char v = p[base + i];
                if (v > 1) lnb = 1;
                else if (v == 1 && ((base + i) & 3)) lod = 1;
            }
            if (lnb) atomicOr(&nonbin, 1);
            if (lod) atomicOr(&oddpos, 1);
            __syncthreads();
            if (tid == 0) g_mask_mode = nonbin ? 2 : (oddpos ? 0 : 1);
        }
        __syncthreads();
    }
    // everyone prefetches their first batch tile 0 before arriving
    if (cta < BB) {
        tile_async(smem + XS_OFF, x + (size_t)cta * (TT * CC));
        CP_COMMIT();
    }
    gbar(&g_tk1, &g_rl1);

    // ============ phase 1: flash attention over owned batches ================
    {
        float* wq_s  = smem + WQ_OFF;
        float* xs    = smem + XS_OFF;
        float* att_s = smem + ATT_OFF;
        float* p_s   = smem + P_OFF;
        float* mrun  = smem + MR_OFF;
        float* srun  = smem + SR_OFF;
        float* fsc   = smem + FS_OFF;
        int*   msk_s = (int*)(smem + MSK_OFF);

        // stage wq once (coalesced float4)
        #pragma unroll 4
        for (int i = tid; i < 4096; i += 256)
            ((float4*)wq_s)[i] = ((const float4*)g_wq)[i];

        const int mode = g_mask_mode;
        const int rg = (wid & 3) * 4;
        const int h0 = (wid >> 2) * 8;
        const int hc = tid >> 4;

        for (int b = cta; b < BB; b += GRID_) {
            const float* xb = x + (size_t)b * (TT * CC);
            __syncthreads();                     // protect smem state reuse
            if (tid < TT) {
                int mv;
                if (mode == 0)      mv = ((const unsigned char*)kpm)[b * TT + tid] != 0;
                else if (mode == 1) mv = ((const int*)kpm)[b * TT + tid] != 0;
                else                mv = ((const float*)kpm)[b * TT + tid] != 0.f;
                msk_s[tid] = mv;
            }
            if (tid < HH) { mrun[tid] = NEGINF_; srun[tid] = 0.f; }

            float4 pacc = make_float4(0.f, 0.f, 0.f, 0.f);

            for (int tile = 0; tile < 4; tile++) {
                int issued = 0;
                if (tile < 3) {
                    tile_async(xs + ((tile + 1) & 1) * 16384, xb + (tile + 1) * 16384);
                    CP_COMMIT(); issued = 1;
                } else if (b + GRID_ < BB) {
                    tile_async(xs, x + (size_t)(b + GRID_) * (TT * CC));
                    CP_COMMIT(); issued = 1;
                }
                if (issued) CP_WAIT1(); else CP_WAIT0();
                __syncthreads();

                float* xt = xs + (tile & 1) * 16384;
                const ulonglong2* xr0 = (const ulonglong2*)(xt + (rg + 0) * CC);
                const ulonglong2* xr1 = (const ulonglong2*)(xt + (rg + 1) * CC);
                const ulonglong2* xr2 = (const ulonglong2*)(xt + (rg + 2) * CC);
                const ulonglong2* xr3 = (const ulonglong2*)(xt + (rg + 3) * CC);
                const ulonglong2* wqp = (const ulonglong2*)(wq_s + h0 * CC);

                unsigned long long acc[4][8];
                #pragma unroll
                for (int r = 0; r < 4; r++)
                    #pragma unroll
                    for (int h = 0; h < 8; h++) acc[r][h] = 0ull;

                #pragma unroll
                for (int it = 0; it < 8; it++) {
                    const int ci = lane + it * 32;
                    ulonglong2 X0 = xr0[ci];
                    ulonglong2 X1 = xr1[ci];
                    ulonglong2 X2 = xr2[ci];
                    ulonglong2 X3 = xr3[ci];
                    #pragma unroll
                    for (int h = 0; h < 8; h++) {
                        ulonglong2 W = wqp[h * (CC / 4) + ci];
                        acc[0][h] = fma2(X0.x, W.x, acc[0][h]); acc[0][h] = fma2(X0.y, W.y, acc[0][h]);
                        acc[1][h] = fma2(X1.x, W.x, acc[1][h]); acc[1][h] = fma2(X1.y, W.y, acc[1][h]);
                        acc[2][h] = fma2(X2.x, W.x, acc[2][h]); acc[2][h] = fma2(X2.y, W.y, acc[2][h]);
                        acc[3][h] = fma2(X3.x, W.x, acc[3][h]); acc[3][h] = fma2(X3.y, W.y, acc[3][h]);
                    }
                }
                #pragma unroll
                for (int r = 0; r < 4; r++) {
                    float sv[8];
                    #pragma unroll
                    for (int h = 0; h < 8; h++) {
                        float lo, hi; upk2(acc[r][h], lo, hi);
                        sv[h] = lo + hi;
                    }
                    #pragma unroll
                    for (int off = 16; off; off >>= 1)
                        #pragma unroll
                        for (int h = 0; h < 8; h++)
                            sv[h] += __shfl_xor_sync(0xffffffffu, sv[h], off);
                    float v = sv[0];
                    #pragma unroll
                    for (int h = 1; h < 8; h++) v = (lane == h) ? sv[h] : v;
                    if (lane < 8)
                        att_s[(h0 + lane) * TT + tile * 16 + rg + r] = v;
                }
                __syncthreads();

                { // flash update
                    const int h  = wid * 2 + (lane >> 4);
                    const int tt = lane & 15;
                    const int tg = tile * 16 + tt;
                    float s_raw  = att_s[h * TT + tg];
                    int   msk    = msk_s[tg];
                    float sm     = msk ? NEGINF_ : s_raw;
                    float tmax   = sm;
                    #pragma unroll
                    for (int off = 8; off; off >>= 1)
                        tmax = fmaxf(tmax, __shfl_xor_sync(0xffffffffu, tmax, off));
                    float m_old = mrun[h];
                    float m_new = fmaxf(m_old, tmax);
                    float p     = msk ? 0.f : __expf(s_raw - m_new);
                    float psum  = p;
                    #pragma unroll
                    for (int off = 8; off; off >>= 1)
                        psum += __shfl_xor_sync(0xffffffffu, psum, off);
                    float f = __expf(m_old - m_new);
                    p_s[h * 16 + tt] = p;
                    if ((lane & 15) == 0) {
                        mrun[h] = m_new;
                        srun[h] = srun[h] * f + psum;
                        fsc[h]  = f;
                    }
                }
                __syncthreads();

                { // pooled accumulation from resident smem tile
                    float f = fsc[hc];
                    pacc.x *= f; pacc.y *= f; pacc.z *= f; pacc.w *= f;
                    const float* xp = xt + tid * 4;
                    const float* pp = p_s + hc * 16;
                    #pragma unroll
                    for (int t = 0; t < 16; t++) {
                        float p = pp[t];
                        float4 v = *(const float4*)(xp + t * CC);
                        pacc.x += p * v.x; pacc.y += p * v.y;
                        pacc.z += p * v.z; pacc.w += p * v.w;
                    }
                }
                __syncthreads();
            }

            { // finalize: attn output + pooled
                const int h  = tid >> 4;
                const int t4 = (tid & 15) * 4;
                float m   = mrun[h];
                float inv = 1.f / srun[h];
                float4 o;
                float* op = &o.x;
                #pragma unroll
                for (int j = 0; j < 4; j++) {
                    int t = t4 + j;
                    op[j] = msk_s[t] ? 0.f : __expf(att_s[h * TT + t] - m) * inv;
                }
                *(float4*)(attn_out + (size_t)b * (HH * TT) + h * TT + t4) = o;

                float invp = 1.f / srun[hc];
                pacc.x *= invp; pacc.y *= invp; pacc.z *= invp; pacc.w *= invp;
                *(float4*)(g_pooled + (size_t)b * CC + tid * 4) = pacc;
            }
        }
    }

    gbar(&g_tk2, &g_rl2);

    // ============ phase 2: MLP, CTAs 0..127 (16 rows each) ===================
    if (cta >= 128) return;
    {
        float* A   = smem + P2_A;
        float* ys  = smem + P2_YS;
        float* y2s = smem + P2_Y2;
        float* mu1 = smem + P2_ST;
        float* rs1 = mu1 + 16;
        float* mu2 = rs1 + 16;
        float* rs2 = mu2 + 16;
        const int b0 = cta * 16;

        // load A (pooled rows), coalesced
        for (int i = tid; i < 4096; i += 256)
            ((float4*)A)[i] = *(const float4*)(g_pooled + (size_t)b0 * CC + i * 4);

        // prefetch W1 k-tiles 0,1
        wtile_async(smem + P2_WB, W1);
        CP_COMMIT();
        wtile_async(smem + P2_WB + 8192, W1 + 8192);
        CP_COMMIT();
        __syncthreads();

        // ---- GEMM1: 16x512x1024, thread = 4 cols x 8 rows ----
        const int cg  = tid & 127;            // cols [4cg, 4cg+4)
        const int rg2 = tid >> 7;             // rows [8rg2, 8rg2+8)
        unsigned long long acc[8][2];
        #pragma unroll
        for (int r = 0; r < 8; r++) { acc[r][0] = 0ull; acc[r][1] = 0ull; }

        const int kk_b = tid >> 4, r_b = tid & 15;   // Asp build assignment
        for (int kt = 0; kt < 64; kt++) {
            float* wb = smem + P2_WB + (kt & 1) * 8192;
            float* sp = smem + P2_SP + (kt & 1) * 2048;
            if (kt < 63) CP_WAIT1(); else CP_WAIT0();
            // build splat tile: Asp[kk][r] = {A[r][kt*16+kk]} x2
            {
                float a = A[r_b * CC + kt * 16 + kk_b];
                ((float2*)sp)[kk_b * 16 + r_b] = make_float2(a, a);
            }
            __syncthreads();
            #pragma unroll
            for (int kk = 0; kk < 16; kk++) {
                ulonglong2 w = *(const ulonglong2*)(wb + kk * 512 + cg * 4);
                const float* aspk = sp + (kk * 16 + rg2 * 8) * 2;
                #pragma unroll
                for (int j = 0; j < 4; j++) {
                    ulonglong2 a2 = *(const ulonglong2*)(aspk + j * 4);
                    acc[2*j  ][0] = fma2(a2.x, w.x, acc[2*j  ][0]);
                    acc[2*j  ][1] = fma2(a2.x, w.y, acc[2*j  ][1]);
                    acc[2*j+1][0] = fma2(a2.y, w.x, acc[2*j+1][0]);
                    acc[2*j+1][1] = fma2(a2.y, w.y, acc[2*j+1][1]);
                }
            }
            __syncthreads();
            if (kt + 2 < 64) {
                wtile_async(smem + P2_WB + (kt & 1) * 8192, W1 + (kt + 2) * 8192);
                CP_COMMIT();
            }
        }
        #pragma unroll
        for (int r = 0; r < 8; r++) {
            float c0, c1, c2, c3;
            upk2(acc[r][0], c0, c1);
            upk2(acc[r][1], c2, c3);
            *(float4*)(ys + (rg2 * 8 + r) * M1M + cg * 4) = make_float4(c0, c1, c2, c3);
        }
        __syncthreads();

        // ---- LN1 ----
        for (int r = wid; r < 16; r += 8) {
            float s = 0.f, ss = 0.f;
            #pragma unroll
            for (int j = 0; j < 16; j++) {
                float v = ys[r * M1M + lane + j * 32];
                s += v; ss += v * v;
            }
            #pragma unroll
            for (int off = 16; off; off >>= 1) {
                s  += __shfl_xor_sync(0xffffffffu, s, off);
                ss += __shfl_xor_sync(0xffffffffu, ss, off);
            }
            if (lane == 0) {
                float mu = s * (1.f / M1M);
                float var = ss * (1.f / M1M) - mu * mu;
                mu1[r] = mu;
                rs1[r] = rsqrtf(var + EPS_);
            }
        }
        __syncthreads();
        {
            float2 gv = ((const float2*)g1)[tid];
            float2 bv = ((const float2*)b1)[tid];
            #pragma unroll
            for (int r = 0; r < 16; r++) {
                float m = mu1[r], rs = rs1[r];
                float2 v = *(float2*)(ys + r * M1M + 2 * tid);
                v.x = fmaxf(0.f, (v.x - m) * rs * gv.x + bv.x);
                v.y = fmaxf(0.f, (v.y - m) * rs * gv.y + bv.y);
                *(float2*)(ys + r * M1M + 2 * tid) = v;
            }
        }
        __syncthreads();

        // ---- GEMM2: 16x128x512, thread = 2 cols x 4 rows, k-tiles of 64 ----
        wtile_async(smem + P2_WB, W2);
        CP_COMMIT();
        wtile_async(smem + P2_WB + 8192, W2 + 8192);
        CP_COMMIT();

        const int cp2 = tid & 63;             // cols [2cp2, 2cp2+2)
        const int rg4 = tid >> 6;             // rows [4rg4, 4rg4+4)
        unsigned long long acc2[4] = {0ull, 0ull, 0ull, 0ull};

        for (int kt = 0; kt < 8; kt++) {
            float* wb = smem + P2_WB + (kt & 1) * 8192;
            float* sp = smem + P2_SP + (kt & 1) * 2048;
            if (kt < 7) CP_WAIT1(); else CP_WAIT0();
            for (int i = tid; i < 1024; i += 256) {
                int kk = i >> 4, r = i & 15;
                float v = ys[r * M1M + kt * 64 + kk];
                ((float2*)sp)[i] = make_float2(v, v);
            }
            __syncthreads();
            #pragma unroll
            for (int kk = 0; kk < 64; kk++) {
                unsigned long long w = *(const unsigned long long*)(wb + kk * 128 + cp2 * 2);
                const float* hk = sp + (kk * 16 + rg4 * 4) * 2;
                ulonglong2 h01 = *(const ulonglong2*)(hk);
                ulonglong2 h23 = *(const ulonglong2*)(hk + 4);
                acc2[0] = fma2(h01.x, w, acc2[0]);
                acc2[1] = fma2(h01.y, w, acc2[1]);
                acc2[2] = fma2(h23.x, w, acc2[2]);
                acc2[3] = fma2(h23.y, w, acc2[3]);
            }
            __syncthreads();
            if (kt + 2 < 8) {
                wtile_async(smem + P2_WB + (kt & 1) * 8192, W2 + (kt + 2) * 8192);
                CP_COMMIT();
            }
        }
        #pragma unroll
        for (int j = 0; j < 4; j++) {
            float c0, c1;
            upk2(acc2[j], c0, c1);
            *(float2*)(y2s + (rg4 * 4 + j) * M2M + cp2 * 2) = make_float2(c0, c1);
        }
        __syncthreads();

        // ---- LN2 + output ----
        for (int r = wid; r < 16; r += 8) {
            float s = 0.f, ss = 0.f;
            #pragma unroll
            for (int j = 0; j < 4; j++) {
                float v = y2s[r * M2M + lane + j * 32];
                s += v; ss += v * v;
            }
            #pragma unroll
            for (int off = 16; off; off >>= 1) {
                s  += __shfl_xor_sync(0xffffffffu, s, off);
                ss += __shfl_xor_sync(0xffffffffu, ss, off);
            }
            if (lane == 0) {
                float mu = s * (1.f / M2M);
                float var = ss * (1.f / M2M) - mu * mu;
                mu2[r] = mu;
                rs2[r] = rsqrtf(var + EPS_);
            }
        }
        __syncthreads();
        {
            const int m  = tid & 127;
            const int rb = (tid >> 7) * 8;
            float gv = g2[m], bv = b2[m];
            #pragma unroll
            for (int j = 0; j < 8; j++) {
                int r = rb + j;
                float v = (y2s[r * M2M + m] - mu2[r]) * rs2[r] * gv + bv;
                out_mlp[(size_t)(b0 + r) * M2M + m] = fmaxf(0.f, v);
            }
        }
    }
}

// ---------------- launcher ----------------
extern "C" void kernel_launch(void* const* d_in, const int* in_sizes, int n_in,
                              void* d_out, int out_size) {
    const float* x     = (const float*)d_in[0];
    const void*  kpm   = d_in[2];
    const float* Wk    = (const float*)d_in[3];
    const float* query = (const float*)d_in[5];
    const float* W1    = (const float*)d_in[6];
    const float* g1    = (const float*)d_in[7];
    const float* b1    = (const float*)d_in[8];
    const float* W2    = (const float*)d_in[9];
    const float* g2    = (const float*)d_in[10];
    const float* b2    = (const float*)d_in[11];

    float* out_mlp  = (float*)d_out;                       // [B, 128]
    float* out_attn = (float*)d_out + (size_t)BB * M2M;    // [B, H, T]

    cudaFuncSetAttribute(k_fused, cudaFuncAttributeMaxDynamicSharedMemorySize,
                         SMEM_F * 4);
    k_fused<<<GRID_, 256, SMEM_F * 4>>>(x, kpm, Wk, query, W1, g1, b1,
                                        W2, g2, b2, out_attn, out_mlp);
}